// round 4
// baseline (speedup 1.0000x reference)
#include <cuda_runtime.h>
#include <math.h>

#define MTOT 32768
#define LDIM 512

// ---------------- scratch (device globals; allocation-free) ----------------
__device__ float g_TW[MTOT * 32 * 2];     // [n*64 + 2t] = cos(t*a_n), +1 = sin
__device__ float g_CS[512 * 2048];        // fwd [j][p | 1024+p]
__device__ float g_WINV[2048 * 512];      // inv [p|1024+p][j]  (has 2/M weight)
__device__ float g_DL[512 * 512];         // L-dim ortho DCT-II matrix
__device__ float g_Q[512 * 512];          // temp
__device__ float g_A1[512 * 512];
__device__ float g_A2[512 * 512];
__device__ float g_A3[512 * 512];
__device__ float g_u1[MTOT], g_u2[MTOT], g_u3[MTOT];
__device__ float g_w1[512], g_w2[512], g_w3[512];
__device__ float g_Yf[2048 * 16384];      // folded X; REUSED as V after U is formed
__device__ float g_U[512 * 16384];        // forward coeffs [j][t*512+l]
__device__ float g_Z2[MTOT * 512];
__device__ float g_Z3[MTOT * 512];

// ---------------- table builders ----------------
__global__ void k_build_tw() {
    int id = blockIdx.x * 256 + threadIdx.x;
    if (id >= MTOT * 32) return;
    int n = id >> 5, t = id & 31;
    int mm = ((2 * n + 1) * t) & 131071;
    float sn, cs;
    sincospif((float)mm * (1.0f / 65536.0f), &sn, &cs);
    g_TW[2 * id + 0] = cs;
    g_TW[2 * id + 1] = sn;
}

__global__ void k_build_cs() {
    int id = blockIdx.x * 256 + threadIdx.x;
    if (id >= 512 * 1024) return;
    int j = id >> 10, p = id & 1023;
    int mm = (j * (2 * p + 1)) & 2047;
    float sn, cs;
    sincospif((float)mm * (1.0f / 1024.0f), &sn, &cs);
    g_CS[j * 2048 + p] = cs;
    g_CS[j * 2048 + 1024 + p] = -sn;
    const float w = 2.0f / 32768.0f;
    g_WINV[p * 512 + j] = cs * w;
    g_WINV[(1024 + p) * 512 + j] = sn * w;
}

__global__ void k_build_dl() {
    int id = blockIdx.x * 256 + threadIdx.x;
    if (id >= 512 * 512) return;
    int k = id >> 9, n = id & 511;
    int mm = (k * (2 * n + 1)) & 2047;
    float cs = cospif((float)mm * (1.0f / 1024.0f));
    float ck = (k == 0) ? 0.04419417382415922f : 0.0625f;
    g_DL[id] = ck * cs;
}

struct C2d { double x, y; };
__device__ __forceinline__ C2d cdiv(C2d a, C2d b) {
    double d = b.x * b.x + b.y * b.y;
    C2d r; r.x = (a.x * b.x + a.y * b.y) / d; r.y = (a.y * b.x - a.x * b.y) / d; return r;
}
__device__ __forceinline__ C2d cmul(C2d a, C2d b) {
    C2d r; r.x = a.x * b.x - a.y * b.y; r.y = a.x * b.y + a.y * b.x; return r;
}
__global__ void k_build_u() {
    int n = blockIdx.x * 256 + threadIdx.x;
    if (n >= MTOT) return;
    long on = 2L * n + 1;
    double s1, c1, s64, c64, s32, c32, s16, c16;
    sincospi((double)on / 65536.0, &s1, &c1);
    sincospi((double)(on & 2047) / 1024.0, &s64, &c64);
    sincospi((double)(on & 4095) / 2048.0, &s32, &c32);
    sincospi((double)(on & 8191) / 4096.0, &s16, &c16);
    C2d numer; numer.x = 1.0; numer.y = (n & 1) ? 1.0 : -1.0;  // 1 - i(-1)^n
    C2d d1;  d1.x  = 1.0 - c1;  d1.y  = -s1;
    C2d d64; d64.x = 1.0 - c64; d64.y = -s64;
    C2d n32; n32.x = 1.0 - c32; n32.y = -s32;
    C2d n16; n16.x = 1.0 - c16; n16.y = -s16;
    double F1 = cdiv(numer, d1).x;
    C2d g = cdiv(numer, d64);
    double F2 = cmul(g, cdiv(n32, d1)).x;
    double F3 = cmul(g, cdiv(n16, d1)).x;
    const double C2M = 0.0078125;               // sqrt(2/32768)
    const double C1M = 0.005524271728019903;    // sqrt(1/32768)
    g_u1[n] = (float)(C2M * (F1 - 1.0) + C1M);
    g_u2[n] = (float)(C2M * (F2 - 1.0) + C1M);
    g_u3[n] = (float)(C2M * (F3 - 1.0) + C1M);
}

__global__ void k_build_w(int Kb, const float* __restrict__ b, float* __restrict__ w) {
    int c = blockIdx.x * 128 + threadIdx.x;
    if (c >= 512) return;
    float s = 0.f;
    for (int k = 0; k < Kb; k++) s += g_DL[k * 512 + c] * b[k];
    w[c] = s;
}

// small GEMMs for A-matrix builds
__global__ void k_gemm_ab(int M, int N, int K, const float* __restrict__ A, int lda,
                          const float* __restrict__ B, int ldb, float* __restrict__ C, int ldc) {
    int n = blockIdx.x * 128 + threadIdx.x, m = blockIdx.y;
    if (n >= N || m >= M) return;
    float s = 0.f;
    for (int k = 0; k < K; k++) s += A[m * lda + k] * B[k * ldb + n];
    C[m * ldc + n] = s;
}
__global__ void k_gemm_atb(int M, int N, int K, const float* __restrict__ A, int lda,
                           const float* __restrict__ B, int ldb, float* __restrict__ C, int ldc) {
    int n = blockIdx.x * 128 + threadIdx.x, m = blockIdx.y;
    if (n >= N || m >= M) return;
    float s = 0.f;
    for (int k = 0; k < K; k++) s += A[k * lda + m] * B[k * ldb + n];
    C[m * ldc + n] = s;
}

// ---------------- fold: X -> Yf ----------------
__global__ void __launch_bounds__(128) k_fold(const float* __restrict__ X) {
    const int p = blockIdx.y;
    const int l = blockIdx.x * 128 + threadIdx.x;
    __shared__ float tw[32][64];
    for (int i = threadIdx.x; i < 2048; i += 128) {
        int q = i >> 6;
        tw[q][i & 63] = g_TW[(((long)(q << 10) + p)) * 64 + (i & 63)];
    }
    __syncthreads();
    float c[32], s[32];
#pragma unroll
    for (int t = 0; t < 32; t++) { c[t] = 0.f; s[t] = 0.f; }
    for (int q = 0; q < 32; q++) {
        float x = X[((q << 10) + p) * 512 + l];
#pragma unroll
        for (int t = 0; t < 32; t++) {
            c[t] += tw[q][2 * t] * x;
            s[t] += tw[q][2 * t + 1] * x;
        }
    }
#pragma unroll
    for (int t = 0; t < 32; t++) {
        g_Yf[p * 16384 + t * 512 + l] = c[t];
        g_Yf[(1024 + p) * 16384 + t * 512 + l] = s[t];
    }
}

// halve k=0 row (j=0,t=0): c_0^2 = (2/M)*(1/2)
__global__ void k_fixup() {
    int l = blockIdx.x * 128 + threadIdx.x;
    if (l < 512) g_U[l] *= 0.5f;
}

// ---------------- combine: V -> Z3 (t<16), Z2 (t<32) ----------------
__global__ void __launch_bounds__(128) k_combine(const float* __restrict__ V) {
    const int p = blockIdx.y;
    const int l = blockIdx.x * 128 + threadIdx.x;
    __shared__ float tw[32][64];
    for (int i = threadIdx.x; i < 2048; i += 128) {
        int q = i >> 6;
        tw[q][i & 63] = g_TW[(((long)(q << 10) + p)) * 64 + (i & 63)];
    }
    __syncthreads();
    float vc[32], vs[32];
#pragma unroll
    for (int t = 0; t < 32; t++) {
        vc[t] = V[p * 16384 + t * 512 + l];
        vs[t] = V[(1024 + p) * 16384 + t * 512 + l];
    }
    for (int q = 0; q < 32; q++) {
        float acc = 0.f;
#pragma unroll
        for (int t = 0; t < 16; t++) acc += tw[q][2 * t] * vc[t] - tw[q][2 * t + 1] * vs[t];
        int n = (q << 10) + p;
        g_Z3[n * 512 + l] = acc;
#pragma unroll
        for (int t = 16; t < 32; t++) acc += tw[q][2 * t] * vc[t] - tw[q][2 * t + 1] * vs[t];
        g_Z2[n * 512 + l] = acc;
    }
}

// ---------------- main SGEMM: C = A(MxK)*B(KxN) [+ u w^T] ----------------
__global__ void __launch_bounds__(256) k_sgemm(
    const float* __restrict__ A, const float* __restrict__ B, float* __restrict__ C,
    int M, int N, int K, int lda, int ldb, int ldc,
    const float* __restrict__ u, const float* __restrict__ w) {
    __shared__ float As[8][128];
    __shared__ float Bs[8][128];
    const int tid = threadIdx.x;
    const int m0 = blockIdx.y * 128, n0 = blockIdx.x * 128;
    const int tx = (tid & 15) * 8;
    const int ty = (tid >> 4) * 8;
    const int arow = tid >> 1, acol = (tid & 1) * 4;
    const int brow = tid >> 5, bcol = (tid & 31) * 4;
    const float* Ap = A + (long)(m0 + arow) * lda + acol;
    const float* Bp = B + (long)brow * ldb + n0 + bcol;
    float acc[8][8];
#pragma unroll
    for (int i = 0; i < 8; i++)
#pragma unroll
        for (int j = 0; j < 8; j++) acc[i][j] = 0.f;

    for (int k0 = 0; k0 < K; k0 += 8) {
        float4 a4 = *(const float4*)(Ap + k0);
        float4 b4 = *(const float4*)(Bp + (long)k0 * ldb);
        As[acol + 0][arow] = a4.x;
        As[acol + 1][arow] = a4.y;
        As[acol + 2][arow] = a4.z;
        As[acol + 3][arow] = a4.w;
        *(float4*)&Bs[brow][bcol] = b4;
        __syncthreads();
#pragma unroll
        for (int kk = 0; kk < 8; kk++) {
            float ar[8], br[8];
            *(float4*)&ar[0] = *(const float4*)&As[kk][ty];
            *(float4*)&ar[4] = *(const float4*)&As[kk][ty + 4];
            *(float4*)&br[0] = *(const float4*)&Bs[kk][tx];
            *(float4*)&br[4] = *(const float4*)&Bs[kk][tx + 4];
#pragma unroll
            for (int i = 0; i < 8; i++)
#pragma unroll
                for (int j = 0; j < 8; j++) acc[i][j] += ar[i] * br[j];
        }
        __syncthreads();
    }
    float ww[8];
    const bool r1 = (u != nullptr);
#pragma unroll
    for (int j = 0; j < 8; j++) ww[j] = r1 ? w[n0 + tx + j] : 0.f;
#pragma unroll
    for (int i = 0; i < 8; i++) {
        float* Cp = C + (long)(m0 + ty + i) * ldc + n0 + tx;
        float ui = r1 ? u[m0 + ty + i] : 0.f;
        float o[8];
#pragma unroll
        for (int j = 0; j < 8; j++) o[j] = acc[i][j] + ui * ww[j];
        *(float4*)Cp = *(float4*)&o[0];
        *(float4*)(Cp + 4) = *(float4*)&o[4];
    }
}

// ---------------- launch ----------------
extern "C" void kernel_launch(void* const* d_in, const int* in_sizes, int n_in,
                              void* d_out, int out_size) {
    const float* X  = (const float*)d_in[0];
    const float* W1 = (const float*)d_in[1];
    const float* b1 = (const float*)d_in[2];
    const float* W2 = (const float*)d_in[3];
    const float* b2 = (const float*)d_in[4];
    const float* W3 = (const float*)d_in[5];
    const float* b3 = (const float*)d_in[6];
    float* out = (float*)d_out;

    float *pCS, *pWINV, *pDL, *pQ, *pA1, *pA2, *pA3;
    float *pu1, *pu2, *pu3, *pw1, *pw2, *pw3, *pYf, *pU, *pZ2, *pZ3;
    cudaGetSymbolAddress((void**)&pCS, g_CS);
    cudaGetSymbolAddress((void**)&pWINV, g_WINV);
    cudaGetSymbolAddress((void**)&pDL, g_DL);
    cudaGetSymbolAddress((void**)&pQ, g_Q);
    cudaGetSymbolAddress((void**)&pA1, g_A1);
    cudaGetSymbolAddress((void**)&pA2, g_A2);
    cudaGetSymbolAddress((void**)&pA3, g_A3);
    cudaGetSymbolAddress((void**)&pu1, g_u1);
    cudaGetSymbolAddress((void**)&pu2, g_u2);
    cudaGetSymbolAddress((void**)&pu3, g_u3);
    cudaGetSymbolAddress((void**)&pw1, g_w1);
    cudaGetSymbolAddress((void**)&pw2, g_w2);
    cudaGetSymbolAddress((void**)&pw3, g_w3);
    cudaGetSymbolAddress((void**)&pYf, g_Yf);
    cudaGetSymbolAddress((void**)&pU, g_U);
    cudaGetSymbolAddress((void**)&pZ2, g_Z2);
    cudaGetSymbolAddress((void**)&pZ3, g_Z3);

    // tables
    k_build_tw<<<(MTOT * 32) / 256, 256>>>();
    k_build_cs<<<(512 * 1024) / 256, 256>>>();
    k_build_dl<<<(512 * 512) / 256, 256>>>();
    k_build_u<<<MTOT / 256, 256>>>();
    k_build_w<<<4, 128>>>(512, b1, pw1);
    k_build_w<<<4, 128>>>(256, b2, pw2);
    k_build_w<<<4, 128>>>(128, b3, pw3);

    // A1 = (W1 @ DL)^T @ DL
    {
        dim3 g((512 + 127) / 128, 512);
        k_gemm_ab<<<g, 128>>>(512, 512, 512, W1, 512, pDL, 512, pQ, 512);
        k_gemm_atb<<<g, 128>>>(512, 512, 512, pQ, 512, pDL, 512, pA1, 512);
    }
    // A2 = (W2 @ DL[0:256])^T @ DL[0:256]
    {
        dim3 g1((512 + 127) / 128, 256), g2((512 + 127) / 128, 512);
        k_gemm_ab<<<g1, 128>>>(256, 512, 256, W2, 256, pDL, 512, pQ, 512);
        k_gemm_atb<<<g2, 128>>>(512, 512, 256, pQ, 512, pDL, 512, pA2, 512);
    }
    // A3 = (W3 @ DL[0:128])^T @ DL[0:128]
    {
        dim3 g1((512 + 127) / 128, 128), g2((512 + 127) / 128, 512);
        k_gemm_ab<<<g1, 128>>>(128, 512, 128, W3, 128, pDL, 512, pQ, 512);
        k_gemm_atb<<<g2, 128>>>(512, 512, 128, pQ, 512, pDL, 512, pA3, 512);
    }

    // fold: X -> Yf
    {
        dim3 g(4, 1024);
        k_fold<<<g, 128>>>(X);
    }
    // U = CS @ Yf   (512 x 16384 x 2048)
    {
        dim3 g(16384 / 128, 512 / 128);
        k_sgemm<<<g, 256>>>(pCS, pYf, pU, 512, 16384, 2048, 2048, 16384, 16384, nullptr, nullptr);
    }
    k_fixup<<<4, 128>>>();
    // V = WINV @ U  (2048 x 16384 x 512) — V aliases Yf (Yf dead after U)
    {
        dim3 g(16384 / 128, 2048 / 128);
        k_sgemm<<<g, 256>>>(pWINV, pU, pYf, 2048, 16384, 512, 512, 16384, 16384, nullptr, nullptr);
    }
    // combine: V -> Z3 (t<16), Z2 (t<32)
    {
        dim3 g(4, 1024);
        k_combine<<<g, 128>>>(pYf);
    }
    // outputs
    {
        dim3 g(512 / 128, MTOT / 128);
        k_sgemm<<<g, 256>>>(X,   pA1, out,        MTOT, 512, 512, 512, 512, 1536, pu1, pw1);
        k_sgemm<<<g, 256>>>(pZ2, pA2, out + 512,  MTOT, 512, 512, 512, 512, 1536, pu2, pw2);
        k_sgemm<<<g, 256>>>(pZ3, pA3, out + 1024, MTOT, 512, 512, 512, 512, 1536, pu3, pw3);
    }
    (void)in_sizes; (void)n_in; (void)out_size;
}

// round 5
// speedup vs baseline: 2.0657x; 2.0657x over previous
#include <cuda_runtime.h>
#include <math.h>
#include <stdint.h>

#define MTOT 32768
#define LDIM 512

// ---------------- scratch (device globals; allocation-free) ----------------
__device__ float g_TW[MTOT * 32 * 2];     // [n*64 + 2t] = cos(t*a_n), +1 = sin
__device__ float g_CS[512 * 2048];        // fwd [j][p | 1024+p]
__device__ float g_WINV[2048 * 512];      // inv [p|1024+p][j]  (has 2/M weight)
__device__ float g_DL[512 * 512];         // L-dim ortho DCT-II matrix
__device__ float g_Q[512 * 512];          // temp
__device__ float g_A1[512 * 512];
__device__ float g_A2[512 * 512];
__device__ float g_A3[512 * 512];
__device__ float g_u1[MTOT], g_u2[MTOT], g_u3[MTOT];
__device__ float g_w1[512], g_w2[512], g_w3[512];
__device__ float g_Yf[2048 * 16384];      // folded X; REUSED as V after U is formed
__device__ float g_U[512 * 16384];        // forward coeffs [j][t*512+l]
__device__ float g_Z2[MTOT * 512];
__device__ float g_Z3[MTOT * 512];

// ---------------- table builders ----------------
__global__ void k_build_tw() {
    int id = blockIdx.x * 256 + threadIdx.x;
    if (id >= MTOT * 32) return;
    int n = id >> 5, t = id & 31;
    int mm = ((2 * n + 1) * t) & 131071;
    float sn, cs;
    sincospif((float)mm * (1.0f / 65536.0f), &sn, &cs);
    g_TW[2 * id + 0] = cs;
    g_TW[2 * id + 1] = sn;
}

__global__ void k_build_cs() {
    int id = blockIdx.x * 256 + threadIdx.x;
    if (id >= 512 * 1024) return;
    int j = id >> 10, p = id & 1023;
    int mm = (j * (2 * p + 1)) & 2047;
    float sn, cs;
    sincospif((float)mm * (1.0f / 1024.0f), &sn, &cs);
    g_CS[j * 2048 + p] = cs;
    g_CS[j * 2048 + 1024 + p] = -sn;
    const float w = 2.0f / 32768.0f;
    g_WINV[p * 512 + j] = cs * w;
    g_WINV[(1024 + p) * 512 + j] = sn * w;
}

__global__ void k_build_dl() {
    int id = blockIdx.x * 256 + threadIdx.x;
    if (id >= 512 * 512) return;
    int k = id >> 9, n = id & 511;
    int mm = (k * (2 * n + 1)) & 2047;
    float cs = cospif((float)mm * (1.0f / 1024.0f));
    float ck = (k == 0) ? 0.04419417382415922f : 0.0625f;
    g_DL[id] = ck * cs;
}

struct C2d { double x, y; };
__device__ __forceinline__ C2d cdiv(C2d a, C2d b) {
    double d = b.x * b.x + b.y * b.y;
    C2d r; r.x = (a.x * b.x + a.y * b.y) / d; r.y = (a.y * b.x - a.x * b.y) / d; return r;
}
__device__ __forceinline__ C2d cmul(C2d a, C2d b) {
    C2d r; r.x = a.x * b.x - a.y * b.y; r.y = a.x * b.y + a.y * b.x; return r;
}
__global__ void k_build_u() {
    int n = blockIdx.x * 256 + threadIdx.x;
    if (n >= MTOT) return;
    long on = 2L * n + 1;
    double s1, c1, s64, c64, s32, c32, s16, c16;
    sincospi((double)on / 65536.0, &s1, &c1);
    sincospi((double)(on & 2047) / 1024.0, &s64, &c64);
    sincospi((double)(on & 4095) / 2048.0, &s32, &c32);
    sincospi((double)(on & 8191) / 4096.0, &s16, &c16);
    C2d numer; numer.x = 1.0; numer.y = (n & 1) ? 1.0 : -1.0;  // 1 - i(-1)^n
    C2d d1;  d1.x  = 1.0 - c1;  d1.y  = -s1;
    C2d d64; d64.x = 1.0 - c64; d64.y = -s64;
    C2d n32; n32.x = 1.0 - c32; n32.y = -s32;
    C2d n16; n16.x = 1.0 - c16; n16.y = -s16;
    double F1 = cdiv(numer, d1).x;
    C2d g = cdiv(numer, d64);
    double F2 = cmul(g, cdiv(n32, d1)).x;
    double F3 = cmul(g, cdiv(n16, d1)).x;
    const double C2M = 0.0078125;               // sqrt(2/32768)
    const double C1M = 0.005524271728019903;    // sqrt(1/32768)
    g_u1[n] = (float)(C2M * (F1 - 1.0) + C1M);
    g_u2[n] = (float)(C2M * (F2 - 1.0) + C1M);
    g_u3[n] = (float)(C2M * (F3 - 1.0) + C1M);
}

__global__ void k_build_w(int Kb, const float* __restrict__ b, float* __restrict__ w) {
    int c = blockIdx.x * 128 + threadIdx.x;
    if (c >= 512) return;
    float s = 0.f;
    for (int k = 0; k < Kb; k++) s += g_DL[k * 512 + c] * b[k];
    w[c] = s;
}

// ---------------- fold: X -> Yf ----------------
__global__ void __launch_bounds__(128) k_fold(const float* __restrict__ X) {
    const int p = blockIdx.y;
    const int l = blockIdx.x * 128 + threadIdx.x;
    __shared__ float tw[32][64];
    for (int i = threadIdx.x; i < 2048; i += 128) {
        int q = i >> 6;
        tw[q][i & 63] = g_TW[(((long)(q << 10) + p)) * 64 + (i & 63)];
    }
    __syncthreads();
    float c[32], s[32];
#pragma unroll
    for (int t = 0; t < 32; t++) { c[t] = 0.f; s[t] = 0.f; }
    for (int q = 0; q < 32; q++) {
        float x = X[((q << 10) + p) * 512 + l];
#pragma unroll
        for (int t = 0; t < 32; t++) {
            c[t] += tw[q][2 * t] * x;
            s[t] += tw[q][2 * t + 1] * x;
        }
    }
#pragma unroll
    for (int t = 0; t < 32; t++) {
        g_Yf[p * 16384 + t * 512 + l] = c[t];
        g_Yf[(1024 + p) * 16384 + t * 512 + l] = s[t];
    }
}

// halve k=0 row (j=0,t=0): c_0^2 = (2/M)*(1/2)
__global__ void k_fixup() {
    int l = blockIdx.x * 128 + threadIdx.x;
    if (l < 512) g_U[l] *= 0.5f;
}

// ---------------- combine: V -> Z3 (t<16), Z2 (t<32) ----------------
__global__ void __launch_bounds__(128) k_combine(const float* __restrict__ V) {
    const int p = blockIdx.y;
    const int l = blockIdx.x * 128 + threadIdx.x;
    __shared__ float tw[32][64];
    for (int i = threadIdx.x; i < 2048; i += 128) {
        int q = i >> 6;
        tw[q][i & 63] = g_TW[(((long)(q << 10) + p)) * 64 + (i & 63)];
    }
    __syncthreads();
    float vc[32], vs[32];
#pragma unroll
    for (int t = 0; t < 32; t++) {
        vc[t] = V[p * 16384 + t * 512 + l];
        vs[t] = V[(1024 + p) * 16384 + t * 512 + l];
    }
    for (int q = 0; q < 32; q++) {
        float acc = 0.f;
#pragma unroll
        for (int t = 0; t < 16; t++) acc += tw[q][2 * t] * vc[t] - tw[q][2 * t + 1] * vs[t];
        int n = (q << 10) + p;
        g_Z3[n * 512 + l] = acc;
#pragma unroll
        for (int t = 16; t < 32; t++) acc += tw[q][2 * t] * vc[t] - tw[q][2 * t + 1] * vs[t];
        g_Z2[n * 512 + l] = acc;
    }
}

// ---------------- tf32 tensor-core GEMM ----------------
// C[M,N] = Alog[M,K] * B[K,N] (+ u w^T), Alog = A or A^T (transA).
// BM=128, BN=128, BK=16; 256 threads, 8 warps in 2(m) x 4(n); warp tile 64x32.
__device__ __forceinline__ uint32_t f2tf(float x) {
    uint32_t r;
    asm("cvt.rna.tf32.f32 %0, %1;" : "=r"(r) : "f"(x));
    return r;
}

__global__ void __launch_bounds__(256) k_mma(
    const float* __restrict__ A, const float* __restrict__ B, float* __restrict__ C,
    int M, int N, int K, int lda, int ldb, int ldc,
    const float* __restrict__ u, const float* __restrict__ w, int transA) {
    __shared__ uint32_t As[16][132];
    __shared__ uint32_t Bs[16][132];
    const int tid = threadIdx.x;
    const int wid = tid >> 5, lane = tid & 31;
    const int wm = wid & 1, wn = wid >> 1;
    const int g = lane >> 2, t4 = lane & 3;
    const int m0 = blockIdx.y * 128, n0 = blockIdx.x * 128;

    float acc[4][4][4];
#pragma unroll
    for (int i = 0; i < 4; i++)
#pragma unroll
        for (int j = 0; j < 4; j++)
#pragma unroll
            for (int r = 0; r < 4; r++) acc[i][j][r] = 0.f;

    // global load mappings
    const int bk = tid >> 4, bn = (tid & 15) * 8;   // B and A-trans: row k, 8 cols
    const int ar = tid >> 1, ak = (tid & 1) * 8;    // A-normal: row m, 8 cols of k

    const float* Aptr0;
    if (transA) Aptr0 = A + (long)bk * lda + m0 + bn;
    else        Aptr0 = A + (long)(m0 + ar) * lda + ak;
    const float* Bptr0 = B + (long)bk * ldb + n0 + bn;

    float4 pa0, pa1, pb0, pb1;
    // prefetch k0 = 0
    if (transA) { pa0 = *(const float4*)(Aptr0);     pa1 = *(const float4*)(Aptr0 + 4); }
    else        { pa0 = *(const float4*)(Aptr0);     pa1 = *(const float4*)(Aptr0 + 4); }
    pb0 = *(const float4*)(Bptr0);
    pb1 = *(const float4*)(Bptr0 + 4);

    for (int k0 = 0; k0 < K; k0 += 16) {
        // store current tile to SMEM (tf32-converted)
        if (transA) {
            uint4 v0, v1;
            v0.x = f2tf(pa0.x); v0.y = f2tf(pa0.y); v0.z = f2tf(pa0.z); v0.w = f2tf(pa0.w);
            v1.x = f2tf(pa1.x); v1.y = f2tf(pa1.y); v1.z = f2tf(pa1.z); v1.w = f2tf(pa1.w);
            *(uint4*)&As[bk][bn] = v0;
            *(uint4*)&As[bk][bn + 4] = v1;
        } else {
            As[ak + 0][ar] = f2tf(pa0.x);
            As[ak + 1][ar] = f2tf(pa0.y);
            As[ak + 2][ar] = f2tf(pa0.z);
            As[ak + 3][ar] = f2tf(pa0.w);
            As[ak + 4][ar] = f2tf(pa1.x);
            As[ak + 5][ar] = f2tf(pa1.y);
            As[ak + 6][ar] = f2tf(pa1.z);
            As[ak + 7][ar] = f2tf(pa1.w);
        }
        {
            uint4 v0, v1;
            v0.x = f2tf(pb0.x); v0.y = f2tf(pb0.y); v0.z = f2tf(pb0.z); v0.w = f2tf(pb0.w);
            v1.x = f2tf(pb1.x); v1.y = f2tf(pb1.y); v1.z = f2tf(pb1.z); v1.w = f2tf(pb1.w);
            *(uint4*)&Bs[bk][bn] = v0;
            *(uint4*)&Bs[bk][bn + 4] = v1;
        }
        __syncthreads();

        // prefetch next tile
        if (k0 + 16 < K) {
            const float* Ap;
            if (transA) Ap = A + (long)(k0 + 16 + bk) * lda + m0 + bn;
            else        Ap = A + (long)(m0 + ar) * lda + k0 + 16 + ak;
            pa0 = *(const float4*)(Ap);
            pa1 = *(const float4*)(Ap + 4);
            const float* Bp = B + (long)(k0 + 16 + bk) * ldb + n0 + bn;
            pb0 = *(const float4*)(Bp);
            pb1 = *(const float4*)(Bp + 4);
        }

        // compute: 2 k-steps of 8
#pragma unroll
        for (int ks = 0; ks < 2; ks++) {
            const int kb = ks * 8;
            uint32_t a[4][4], b[4][2];
#pragma unroll
            for (int mi = 0; mi < 4; mi++) {
                int row = wm * 64 + mi * 16 + g;
                a[mi][0] = As[kb + t4][row];
                a[mi][1] = As[kb + t4][row + 8];
                a[mi][2] = As[kb + t4 + 4][row];
                a[mi][3] = As[kb + t4 + 4][row + 8];
            }
#pragma unroll
            for (int nj = 0; nj < 4; nj++) {
                int col = wn * 32 + nj * 8 + g;
                b[nj][0] = Bs[kb + t4][col];
                b[nj][1] = Bs[kb + t4 + 4][col];
            }
#pragma unroll
            for (int mi = 0; mi < 4; mi++)
#pragma unroll
                for (int nj = 0; nj < 4; nj++) {
                    asm("mma.sync.aligned.m16n8k8.row.col.f32.tf32.tf32.f32 "
                        "{%0,%1,%2,%3}, {%4,%5,%6,%7}, {%8,%9}, {%0,%1,%2,%3};"
                        : "+f"(acc[mi][nj][0]), "+f"(acc[mi][nj][1]),
                          "+f"(acc[mi][nj][2]), "+f"(acc[mi][nj][3])
                        : "r"(a[mi][0]), "r"(a[mi][1]), "r"(a[mi][2]), "r"(a[mi][3]),
                          "r"(b[nj][0]), "r"(b[nj][1]));
                }
        }
        __syncthreads();
    }

    // epilogue
    const bool r1 = (u != nullptr);
#pragma unroll
    for (int mi = 0; mi < 4; mi++) {
        int r = wm * 64 + mi * 16 + g;
        float u0 = 0.f, u1 = 0.f;
        if (r1) { u0 = u[m0 + r]; u1 = u[m0 + r + 8]; }
#pragma unroll
        for (int nj = 0; nj < 4; nj++) {
            int c = wn * 32 + nj * 8 + t4 * 2;
            float w0 = 0.f, w1 = 0.f;
            if (r1) { w0 = w[n0 + c]; w1 = w[n0 + c + 1]; }
            float2 v0, v1;
            v0.x = acc[mi][nj][0] + u0 * w0;
            v0.y = acc[mi][nj][1] + u0 * w1;
            v1.x = acc[mi][nj][2] + u1 * w0;
            v1.y = acc[mi][nj][3] + u1 * w1;
            *(float2*)(C + (long)(m0 + r) * ldc + n0 + c) = v0;
            *(float2*)(C + (long)(m0 + r + 8) * ldc + n0 + c) = v1;
        }
    }
}

// ---------------- launch ----------------
extern "C" void kernel_launch(void* const* d_in, const int* in_sizes, int n_in,
                              void* d_out, int out_size) {
    const float* X  = (const float*)d_in[0];
    const float* W1 = (const float*)d_in[1];
    const float* b1 = (const float*)d_in[2];
    const float* W2 = (const float*)d_in[3];
    const float* b2 = (const float*)d_in[4];
    const float* W3 = (const float*)d_in[5];
    const float* b3 = (const float*)d_in[6];
    float* out = (float*)d_out;

    float *pCS, *pWINV, *pDL, *pQ, *pA1, *pA2, *pA3;
    float *pu1, *pu2, *pu3, *pw1, *pw2, *pw3, *pYf, *pU, *pZ2, *pZ3;
    cudaGetSymbolAddress((void**)&pCS, g_CS);
    cudaGetSymbolAddress((void**)&pWINV, g_WINV);
    cudaGetSymbolAddress((void**)&pDL, g_DL);
    cudaGetSymbolAddress((void**)&pQ, g_Q);
    cudaGetSymbolAddress((void**)&pA1, g_A1);
    cudaGetSymbolAddress((void**)&pA2, g_A2);
    cudaGetSymbolAddress((void**)&pA3, g_A3);
    cudaGetSymbolAddress((void**)&pu1, g_u1);
    cudaGetSymbolAddress((void**)&pu2, g_u2);
    cudaGetSymbolAddress((void**)&pu3, g_u3);
    cudaGetSymbolAddress((void**)&pw1, g_w1);
    cudaGetSymbolAddress((void**)&pw2, g_w2);
    cudaGetSymbolAddress((void**)&pw3, g_w3);
    cudaGetSymbolAddress((void**)&pYf, g_Yf);
    cudaGetSymbolAddress((void**)&pU, g_U);
    cudaGetSymbolAddress((void**)&pZ2, g_Z2);
    cudaGetSymbolAddress((void**)&pZ3, g_Z3);

    // tables
    k_build_tw<<<(MTOT * 32) / 256, 256>>>();
    k_build_cs<<<(512 * 1024) / 256, 256>>>();
    k_build_dl<<<(512 * 512) / 256, 256>>>();
    k_build_u<<<MTOT / 256, 256>>>();
    k_build_w<<<4, 128>>>(512, b1, pw1);
    k_build_w<<<4, 128>>>(256, b2, pw2);
    k_build_w<<<4, 128>>>(128, b3, pw3);

    // A1 = (W1 @ DL)^T @ DL
    k_mma<<<dim3(4, 4), 256>>>(W1, pDL, pQ, 512, 512, 512, 512, 512, 512, nullptr, nullptr, 0);
    k_mma<<<dim3(4, 4), 256>>>(pQ, pDL, pA1, 512, 512, 512, 512, 512, 512, nullptr, nullptr, 1);
    // A2 = (W2 @ DL[0:256])^T @ DL[0:256]
    k_mma<<<dim3(4, 2), 256>>>(W2, pDL, pQ, 256, 512, 256, 256, 512, 512, nullptr, nullptr, 0);
    k_mma<<<dim3(4, 4), 256>>>(pQ, pDL, pA2, 512, 512, 256, 512, 512, 512, nullptr, nullptr, 1);
    // A3 = (W3 @ DL[0:128])^T @ DL[0:128]
    k_mma<<<dim3(4, 1), 256>>>(W3, pDL, pQ, 128, 512, 128, 128, 512, 512, nullptr, nullptr, 0);
    k_mma<<<dim3(4, 4), 256>>>(pQ, pDL, pA3, 512, 512, 128, 512, 512, 512, nullptr, nullptr, 1);

    // fold: X -> Yf
    {
        dim3 g(4, 1024);
        k_fold<<<g, 128>>>(X);
    }
    // U = CS @ Yf   (512 x 16384 x 2048)
    k_mma<<<dim3(128, 4), 256>>>(pCS, pYf, pU, 512, 16384, 2048, 2048, 16384, 16384,
                                 nullptr, nullptr, 0);
    k_fixup<<<4, 128>>>();
    // V = WINV @ U  (2048 x 16384 x 512) — V aliases Yf
    k_mma<<<dim3(128, 16), 256>>>(pWINV, pU, pYf, 2048, 16384, 512, 512, 16384, 16384,
                                  nullptr, nullptr, 0);
    // combine: V -> Z3 (t<16), Z2 (t<32)
    {
        dim3 g(4, 1024);
        k_combine<<<g, 128>>>(pYf);
    }
    // outputs
    k_mma<<<dim3(4, 256), 256>>>(X,   pA1, out,        MTOT, 512, 512, 512, 512, 1536, pu1, pw1, 0);
    k_mma<<<dim3(4, 256), 256>>>(pZ2, pA2, out + 512,  MTOT, 512, 512, 512, 512, 1536, pu2, pw2, 0);
    k_mma<<<dim3(4, 256), 256>>>(pZ3, pA3, out + 1024, MTOT, 512, 512, 512, 512, 1536, pu3, pw3, 0);
    (void)in_sizes; (void)n_in; (void)out_size;
}

// round 6
// speedup vs baseline: 2.8447x; 1.3771x over previous
#include <cuda_runtime.h>
#include <math.h>
#include <stdint.h>

#define MTOT 32768
#define LDIM 512

// ---------------- scratch (device globals; allocation-free) ----------------
__device__ __align__(128) float g_TW[MTOT * 32 * 2];
__device__ __align__(128) float g_CS[512 * 2048];
__device__ __align__(128) float g_WINV[2048 * 512];
__device__ __align__(128) float g_DL[512 * 512];
__device__ __align__(128) float g_Q[512 * 512];
__device__ __align__(128) float g_A1[512 * 512];
__device__ __align__(128) float g_A2[512 * 512];
__device__ __align__(128) float g_A3[512 * 512];
__device__ __align__(128) float g_u1[MTOT];
__device__ __align__(128) float g_u2[MTOT];
__device__ __align__(128) float g_u3[MTOT];
__device__ __align__(128) float g_w1[512];
__device__ __align__(128) float g_w2[512];
__device__ __align__(128) float g_w3[512];
__device__ __align__(128) float g_Yf[2048 * 16384];   // fold out; reused as V
__device__ __align__(128) float g_U[512 * 16384];
__device__ __align__(128) float g_Z2[MTOT * 512];
__device__ __align__(128) float g_Z3[MTOT * 512];
__device__ __align__(128) float g_Xr[MTOT * 512];     // tf32-rounded copy of X

__device__ __forceinline__ uint32_t f2tf(float x) {
    uint32_t r;
    asm("cvt.rna.tf32.f32 %0, %1;" : "=r"(r) : "f"(x));
    return r;
}
__device__ __forceinline__ float rtf(float x) { return __uint_as_float(f2tf(x)); }

// ---------------- table builders ----------------
__global__ void k_build_tw() {
    int id = blockIdx.x * 256 + threadIdx.x;
    if (id >= MTOT * 32) return;
    int n = id >> 5, t = id & 31;
    int mm = ((2 * n + 1) * t) & 131071;
    float sn, cs;
    sincospif((float)mm * (1.0f / 65536.0f), &sn, &cs);
    g_TW[2 * id + 0] = cs;
    g_TW[2 * id + 1] = sn;
}

__global__ void k_build_cs() {   // pre-rounded to tf32
    int id = blockIdx.x * 256 + threadIdx.x;
    if (id >= 512 * 1024) return;
    int j = id >> 10, p = id & 1023;
    int mm = (j * (2 * p + 1)) & 2047;
    float sn, cs;
    sincospif((float)mm * (1.0f / 1024.0f), &sn, &cs);
    g_CS[j * 2048 + p] = rtf(cs);
    g_CS[j * 2048 + 1024 + p] = rtf(-sn);
    const float w = 2.0f / 32768.0f;
    g_WINV[p * 512 + j] = rtf(cs * w);
    g_WINV[(1024 + p) * 512 + j] = rtf(sn * w);
}

__global__ void k_build_dl() {
    int id = blockIdx.x * 256 + threadIdx.x;
    if (id >= 512 * 512) return;
    int k = id >> 9, n = id & 511;
    int mm = (k * (2 * n + 1)) & 2047;
    float cs = cospif((float)mm * (1.0f / 1024.0f));
    float ck = (k == 0) ? 0.04419417382415922f : 0.0625f;
    g_DL[id] = ck * cs;
}

struct C2d { double x, y; };
__device__ __forceinline__ C2d cdiv(C2d a, C2d b) {
    double d = b.x * b.x + b.y * b.y;
    C2d r; r.x = (a.x * b.x + a.y * b.y) / d; r.y = (a.y * b.x - a.x * b.y) / d; return r;
}
__device__ __forceinline__ C2d cmul(C2d a, C2d b) {
    C2d r; r.x = a.x * b.x - a.y * b.y; r.y = a.x * b.y + a.y * b.x; return r;
}
__global__ void k_build_u() {
    int n = blockIdx.x * 256 + threadIdx.x;
    if (n >= MTOT) return;
    long on = 2L * n + 1;
    double s1, c1, s64, c64, s32, c32, s16, c16;
    sincospi((double)on / 65536.0, &s1, &c1);
    sincospi((double)(on & 2047) / 1024.0, &s64, &c64);
    sincospi((double)(on & 4095) / 2048.0, &s32, &c32);
    sincospi((double)(on & 8191) / 4096.0, &s16, &c16);
    C2d numer; numer.x = 1.0; numer.y = (n & 1) ? 1.0 : -1.0;
    C2d d1;  d1.x  = 1.0 - c1;  d1.y  = -s1;
    C2d d64; d64.x = 1.0 - c64; d64.y = -s64;
    C2d n32; n32.x = 1.0 - c32; n32.y = -s32;
    C2d n16; n16.x = 1.0 - c16; n16.y = -s16;
    double F1 = cdiv(numer, d1).x;
    C2d g = cdiv(numer, d64);
    double F2 = cmul(g, cdiv(n32, d1)).x;
    double F3 = cmul(g, cdiv(n16, d1)).x;
    const double C2M = 0.0078125;
    const double C1M = 0.005524271728019903;
    g_u1[n] = (float)(C2M * (F1 - 1.0) + C1M);
    g_u2[n] = (float)(C2M * (F2 - 1.0) + C1M);
    g_u3[n] = (float)(C2M * (F3 - 1.0) + C1M);
}

__global__ void k_build_w(int Kb, const float* __restrict__ b, float* __restrict__ w) {
    int c = blockIdx.x * 128 + threadIdx.x;
    if (c >= 512) return;
    float s = 0.f;
    for (int k = 0; k < Kb; k++) s += g_DL[k * 512 + c] * b[k];
    w[c] = s;
}

// ---------------- fold: X -> Yf (tf32-rounded) + Xr ----------------
__global__ void __launch_bounds__(128) k_fold(const float* __restrict__ X) {
    const int p = blockIdx.y;
    const int l = blockIdx.x * 128 + threadIdx.x;
    __shared__ float tw[32][64];
    for (int i = threadIdx.x; i < 2048; i += 128) {
        int q = i >> 6;
        tw[q][i & 63] = g_TW[(((long)(q << 10) + p)) * 64 + (i & 63)];
    }
    __syncthreads();
    float c[32], s[32];
#pragma unroll
    for (int t = 0; t < 32; t++) { c[t] = 0.f; s[t] = 0.f; }
    for (int q = 0; q < 32; q++) {
        int n = (q << 10) + p;
        float x = X[n * 512 + l];
        g_Xr[n * 512 + l] = rtf(x);
#pragma unroll
        for (int t = 0; t < 32; t++) {
            c[t] += tw[q][2 * t] * x;
            s[t] += tw[q][2 * t + 1] * x;
        }
    }
#pragma unroll
    for (int t = 0; t < 32; t++) {
        g_Yf[p * 16384 + t * 512 + l] = rtf(c[t]);
        g_Yf[(1024 + p) * 16384 + t * 512 + l] = rtf(s[t]);
    }
}

__global__ void k_fixup() {
    int l = blockIdx.x * 128 + threadIdx.x;
    if (l < 512) g_U[l] *= 0.5f;   // exact scaling, stays tf32-representable
}

// ---------------- combine: V -> Z3 (t<16), Z2 (t<32), tf32-rounded ----------------
__global__ void __launch_bounds__(128) k_combine(const float* __restrict__ V) {
    const int p = blockIdx.y;
    const int l = blockIdx.x * 128 + threadIdx.x;
    __shared__ float tw[32][64];
    for (int i = threadIdx.x; i < 2048; i += 128) {
        int q = i >> 6;
        tw[q][i & 63] = g_TW[(((long)(q << 10) + p)) * 64 + (i & 63)];
    }
    __syncthreads();
    float vc[32], vs[32];
#pragma unroll
    for (int t = 0; t < 32; t++) {
        vc[t] = V[p * 16384 + t * 512 + l];
        vs[t] = V[(1024 + p) * 16384 + t * 512 + l];
    }
    for (int q = 0; q < 32; q++) {
        float acc = 0.f;
#pragma unroll
        for (int t = 0; t < 16; t++) acc += tw[q][2 * t] * vc[t] - tw[q][2 * t + 1] * vs[t];
        int n = (q << 10) + p;
        g_Z3[n * 512 + l] = rtf(acc);
#pragma unroll
        for (int t = 16; t < 32; t++) acc += tw[q][2 * t] * vc[t] - tw[q][2 * t + 1] * vs[t];
        g_Z2[n * 512 + l] = rtf(acc);
    }
}

// ---------------- small tf32 GEMM (builder matrices only) ----------------
__global__ void __launch_bounds__(256) k_mma(
    const float* __restrict__ A, const float* __restrict__ B, float* __restrict__ C,
    int M, int N, int K, int lda, int ldb, int ldc, int transA, int roundC) {
    __shared__ uint32_t As[16][132];
    __shared__ uint32_t Bs[16][132];
    const int tid = threadIdx.x;
    const int wid = tid >> 5, lane = tid & 31;
    const int wm = wid & 1, wn = wid >> 1;
    const int g = lane >> 2, t4 = lane & 3;
    const int m0 = blockIdx.y * 128, n0 = blockIdx.x * 128;

    float acc[4][4][4];
#pragma unroll
    for (int i = 0; i < 4; i++)
#pragma unroll
        for (int j = 0; j < 4; j++)
#pragma unroll
            for (int r = 0; r < 4; r++) acc[i][j][r] = 0.f;

    const int bk = tid >> 4, bn = (tid & 15) * 8;
    const int ar = tid >> 1, ak = (tid & 1) * 8;

    for (int k0 = 0; k0 < K; k0 += 16) {
        const float* Ap;
        if (transA) Ap = A + (long)(k0 + bk) * lda + m0 + bn;
        else        Ap = A + (long)(m0 + ar) * lda + k0 + ak;
        float4 pa0 = *(const float4*)(Ap);
        float4 pa1 = *(const float4*)(Ap + 4);
        const float* Bp = B + (long)(k0 + bk) * ldb + n0 + bn;
        float4 pb0 = *(const float4*)(Bp);
        float4 pb1 = *(const float4*)(Bp + 4);
        if (transA) {
            uint4 v0, v1;
            v0.x = f2tf(pa0.x); v0.y = f2tf(pa0.y); v0.z = f2tf(pa0.z); v0.w = f2tf(pa0.w);
            v1.x = f2tf(pa1.x); v1.y = f2tf(pa1.y); v1.z = f2tf(pa1.z); v1.w = f2tf(pa1.w);
            *(uint4*)&As[bk][bn] = v0;
            *(uint4*)&As[bk][bn + 4] = v1;
        } else {
            As[ak + 0][ar] = f2tf(pa0.x);
            As[ak + 1][ar] = f2tf(pa0.y);
            As[ak + 2][ar] = f2tf(pa0.z);
            As[ak + 3][ar] = f2tf(pa0.w);
            As[ak + 4][ar] = f2tf(pa1.x);
            As[ak + 5][ar] = f2tf(pa1.y);
            As[ak + 6][ar] = f2tf(pa1.z);
            As[ak + 7][ar] = f2tf(pa1.w);
        }
        {
            uint4 v0, v1;
            v0.x = f2tf(pb0.x); v0.y = f2tf(pb0.y); v0.z = f2tf(pb0.z); v0.w = f2tf(pb0.w);
            v1.x = f2tf(pb1.x); v1.y = f2tf(pb1.y); v1.z = f2tf(pb1.z); v1.w = f2tf(pb1.w);
            *(uint4*)&Bs[bk][bn] = v0;
            *(uint4*)&Bs[bk][bn + 4] = v1;
        }
        __syncthreads();
#pragma unroll
        for (int ks = 0; ks < 2; ks++) {
            const int kb = ks * 8;
            uint32_t a[4][4], b[4][2];
#pragma unroll
            for (int mi = 0; mi < 4; mi++) {
                int row = wm * 64 + mi * 16 + g;
                a[mi][0] = As[kb + t4][row];
                a[mi][1] = As[kb + t4][row + 8];
                a[mi][2] = As[kb + t4 + 4][row];
                a[mi][3] = As[kb + t4 + 4][row + 8];
            }
#pragma unroll
            for (int nj = 0; nj < 4; nj++) {
                int col = wn * 32 + nj * 8 + g;
                b[nj][0] = Bs[kb + t4][col];
                b[nj][1] = Bs[kb + t4 + 4][col];
            }
#pragma unroll
            for (int mi = 0; mi < 4; mi++)
#pragma unroll
                for (int nj = 0; nj < 4; nj++) {
                    asm("mma.sync.aligned.m16n8k8.row.col.f32.tf32.tf32.f32 "
                        "{%0,%1,%2,%3}, {%4,%5,%6,%7}, {%8,%9}, {%0,%1,%2,%3};"
                        : "+f"(acc[mi][nj][0]), "+f"(acc[mi][nj][1]),
                          "+f"(acc[mi][nj][2]), "+f"(acc[mi][nj][3])
                        : "r"(a[mi][0]), "r"(a[mi][1]), "r"(a[mi][2]), "r"(a[mi][3]),
                          "r"(b[nj][0]), "r"(b[nj][1]));
                }
        }
        __syncthreads();
    }
#pragma unroll
    for (int mi = 0; mi < 4; mi++) {
        int r = wm * 64 + mi * 16 + g;
#pragma unroll
        for (int nj = 0; nj < 4; nj++) {
            int c = wn * 32 + nj * 8 + t4 * 2;
            float2 v0, v1;
            v0.x = acc[mi][nj][0]; v0.y = acc[mi][nj][1];
            v1.x = acc[mi][nj][2]; v1.y = acc[mi][nj][3];
            if (roundC) {
                v0.x = rtf(v0.x); v0.y = rtf(v0.y);
                v1.x = rtf(v1.x); v1.y = rtf(v1.y);
            }
            *(float2*)(C + (long)(m0 + r) * ldc + n0 + c) = v0;
            *(float2*)(C + (long)(m0 + r + 8) * ldc + n0 + c) = v1;
        }
    }
}

// ---------------- pipelined tf32 GEMM (inputs pre-rounded to tf32) ----------------
// C[M,N] = A[M,K]*B[K,N] (+ u w^T). BM=BN=128, BK=16, 4-stage cp.async.
#define NSTG 4
#define SM_A_STRIDE 20      // [128][20] per stage
#define SM_B_STRIDE 136     // [16][136] per stage
#define SM_A_STAGE (128 * SM_A_STRIDE)
#define SM_B_STAGE (16 * SM_B_STRIDE)
#define SMEM_BYTES ((NSTG * (SM_A_STAGE + SM_B_STAGE)) * 4)

__device__ __forceinline__ void cp16(float* dst, const float* src) {
    uint32_t d = (uint32_t)__cvta_generic_to_shared(dst);
    asm volatile("cp.async.cg.shared.global [%0], [%1], 16;" :: "r"(d), "l"(src));
}

__global__ void __launch_bounds__(256, 2) k_mma2(
    const float* __restrict__ A, const float* __restrict__ B, float* __restrict__ C,
    int M, int N, int K, int lda, int ldb, int ldc,
    const float* __restrict__ u, const float* __restrict__ w, int roundC) {
    extern __shared__ float sm[];
    float* smA = sm;                      // [NSTG][128][20]
    float* smB = sm + NSTG * SM_A_STAGE;  // [NSTG][16][136]
    const int tid = threadIdx.x;
    const int wid = tid >> 5, lane = tid & 31;
    const int wm = wid & 1, wn = wid >> 1;
    const int g = lane >> 2, t4 = lane & 3;
    const int m0 = blockIdx.y * 128, n0 = blockIdx.x * 128;
    const int KT = K >> 4;

    // per-thread load coords
    const int arow0 = tid >> 2, akp = (tid & 3) << 2;      // A chunk 0: rows 0..63
    const int bkr0 = tid >> 5, bnp = (tid & 31) << 2;      // B chunk 0: k 0..7

    float acc[4][4][4];
#pragma unroll
    for (int i = 0; i < 4; i++)
#pragma unroll
        for (int j = 0; j < 4; j++)
#pragma unroll
            for (int r = 0; r < 4; r++) acc[i][j][r] = 0.f;

#define ISSUE(sname, ktile) do {                                            \
        int _kk = (ktile) << 4;                                             \
        float* _a = smA + (sname) * SM_A_STAGE;                             \
        float* _b = smB + (sname) * SM_B_STAGE;                             \
        cp16(_a + arow0 * SM_A_STRIDE + akp,                                \
             A + (long)(m0 + arow0) * lda + _kk + akp);                     \
        cp16(_a + (arow0 + 64) * SM_A_STRIDE + akp,                         \
             A + (long)(m0 + arow0 + 64) * lda + _kk + akp);                \
        cp16(_b + bkr0 * SM_B_STRIDE + bnp,                                 \
             B + (long)(_kk + bkr0) * ldb + n0 + bnp);                      \
        cp16(_b + (bkr0 + 8) * SM_B_STRIDE + bnp,                           \
             B + (long)(_kk + bkr0 + 8) * ldb + n0 + bnp);                  \
        asm volatile("cp.async.commit_group;");                             \
    } while (0)

#pragma unroll
    for (int s = 0; s < NSTG - 1; s++)
        if (s < KT) ISSUE(s, s);

    for (int kt = 0; kt < KT; kt++) {
        asm volatile("cp.async.wait_group %0;" :: "n"(NSTG - 2));
        __syncthreads();
        int nt = kt + NSTG - 1;
        if (nt < KT) ISSUE(nt & (NSTG - 1), nt);
        const int s = kt & (NSTG - 1);
        const float* sa = smA + s * SM_A_STAGE;
        const float* sb = smB + s * SM_B_STAGE;
#pragma unroll
        for (int ks = 0; ks < 2; ks++) {
            const int kb = ks * 8;
            uint32_t a[4][4], b[4][2];
#pragma unroll
            for (int mi = 0; mi < 4; mi++) {
                int row = wm * 64 + mi * 16 + g;
                a[mi][0] = __float_as_uint(sa[row * SM_A_STRIDE + kb + t4]);
                a[mi][1] = __float_as_uint(sa[(row + 8) * SM_A_STRIDE + kb + t4]);
                a[mi][2] = __float_as_uint(sa[row * SM_A_STRIDE + kb + t4 + 4]);
                a[mi][3] = __float_as_uint(sa[(row + 8) * SM_A_STRIDE + kb + t4 + 4]);
            }
#pragma unroll
            for (int nj = 0; nj < 4; nj++) {
                int col = wn * 32 + nj * 8 + g;
                b[nj][0] = __float_as_uint(sb[(kb + t4) * SM_B_STRIDE + col]);
                b[nj][1] = __float_as_uint(sb[(kb + t4 + 4) * SM_B_STRIDE + col]);
            }
#pragma unroll
            for (int mi = 0; mi < 4; mi++)
#pragma unroll
                for (int nj = 0; nj < 4; nj++) {
                    asm("mma.sync.aligned.m16n8k8.row.col.f32.tf32.tf32.f32 "
                        "{%0,%1,%2,%3}, {%4,%5,%6,%7}, {%8,%9}, {%0,%1,%2,%3};"
                        : "+f"(acc[mi][nj][0]), "+f"(acc[mi][nj][1]),
                          "+f"(acc[mi][nj][2]), "+f"(acc[mi][nj][3])
                        : "r"(a[mi][0]), "r"(a[mi][1]), "r"(a[mi][2]), "r"(a[mi][3]),
                          "r"(b[nj][0]), "r"(b[nj][1]));
                }
        }
    }

    const bool r1 = (u != nullptr);
#pragma unroll
    for (int mi = 0; mi < 4; mi++) {
        int r = wm * 64 + mi * 16 + g;
        float u0 = 0.f, u1 = 0.f;
        if (r1) { u0 = u[m0 + r]; u1 = u[m0 + r + 8]; }
#pragma unroll
        for (int nj = 0; nj < 4; nj++) {
            int c = wn * 32 + nj * 8 + t4 * 2;
            float w0 = 0.f, w1 = 0.f;
            if (r1) { w0 = w[n0 + c]; w1 = w[n0 + c + 1]; }
            float2 v0, v1;
            v0.x = acc[mi][nj][0] + u0 * w0;
            v0.y = acc[mi][nj][1] + u0 * w1;
            v1.x = acc[mi][nj][2] + u1 * w0;
            v1.y = acc[mi][nj][3] + u1 * w1;
            if (roundC) {
                v0.x = rtf(v0.x); v0.y = rtf(v0.y);
                v1.x = rtf(v1.x); v1.y = rtf(v1.y);
            }
            *(float2*)(C + (long)(m0 + r) * ldc + n0 + c) = v0;
            *(float2*)(C + (long)(m0 + r + 8) * ldc + n0 + c) = v1;
        }
    }
}

// ---------------- launch ----------------
extern "C" void kernel_launch(void* const* d_in, const int* in_sizes, int n_in,
                              void* d_out, int out_size) {
    const float* X  = (const float*)d_in[0];
    const float* W1 = (const float*)d_in[1];
    const float* b1 = (const float*)d_in[2];
    const float* W2 = (const float*)d_in[3];
    const float* b2 = (const float*)d_in[4];
    const float* W3 = (const float*)d_in[5];
    const float* b3 = (const float*)d_in[6];
    float* out = (float*)d_out;

    float *pCS, *pWINV, *pDL, *pQ, *pA1, *pA2, *pA3;
    float *pu1, *pu2, *pu3, *pw1, *pw2, *pw3, *pYf, *pU, *pZ2, *pZ3, *pXr;
    cudaGetSymbolAddress((void**)&pCS, g_CS);
    cudaGetSymbolAddress((void**)&pWINV, g_WINV);
    cudaGetSymbolAddress((void**)&pDL, g_DL);
    cudaGetSymbolAddress((void**)&pQ, g_Q);
    cudaGetSymbolAddress((void**)&pA1, g_A1);
    cudaGetSymbolAddress((void**)&pA2, g_A2);
    cudaGetSymbolAddress((void**)&pA3, g_A3);
    cudaGetSymbolAddress((void**)&pu1, g_u1);
    cudaGetSymbolAddress((void**)&pu2, g_u2);
    cudaGetSymbolAddress((void**)&pu3, g_u3);
    cudaGetSymbolAddress((void**)&pw1, g_w1);
    cudaGetSymbolAddress((void**)&pw2, g_w2);
    cudaGetSymbolAddress((void**)&pw3, g_w3);
    cudaGetSymbolAddress((void**)&pYf, g_Yf);
    cudaGetSymbolAddress((void**)&pU, g_U);
    cudaGetSymbolAddress((void**)&pZ2, g_Z2);
    cudaGetSymbolAddress((void**)&pZ3, g_Z3);
    cudaGetSymbolAddress((void**)&pXr, g_Xr);

    cudaFuncSetAttribute(k_mma2, cudaFuncAttributeMaxDynamicSharedMemorySize, SMEM_BYTES);

    // tables
    k_build_tw<<<(MTOT * 32) / 256, 256>>>();
    k_build_cs<<<(512 * 1024) / 256, 256>>>();
    k_build_dl<<<(512 * 512) / 256, 256>>>();
    k_build_u<<<MTOT / 256, 256>>>();
    k_build_w<<<4, 128>>>(512, b1, pw1);
    k_build_w<<<4, 128>>>(256, b2, pw2);
    k_build_w<<<4, 128>>>(128, b3, pw3);

    // A1 = (W1 @ DL)^T @ DL   (rounded outputs; consumed raw by k_mma2)
    k_mma<<<dim3(4, 4), 256>>>(W1, pDL, pQ, 512, 512, 512, 512, 512, 512, 0, 0);
    k_mma<<<dim3(4, 4), 256>>>(pQ, pDL, pA1, 512, 512, 512, 512, 512, 512, 1, 1);
    // A2 = (W2 @ DL[0:256])^T @ DL[0:256]
    k_mma<<<dim3(4, 2), 256>>>(W2, pDL, pQ, 256, 512, 256, 256, 512, 512, 0, 0);
    k_mma<<<dim3(4, 4), 256>>>(pQ, pDL, pA2, 512, 512, 256, 512, 512, 512, 1, 1);
    // A3 = (W3 @ DL[0:128])^T @ DL[0:128]
    k_mma<<<dim3(4, 1), 256>>>(W3, pDL, pQ, 128, 512, 128, 128, 512, 512, 0, 0);
    k_mma<<<dim3(4, 4), 256>>>(pQ, pDL, pA3, 512, 512, 128, 512, 512, 512, 1, 1);

    // fold: X -> Yf (rounded) + Xr
    k_fold<<<dim3(4, 1024), 128>>>(X);

    // U = CS @ Yf   (512 x 16384 x 2048), rounded (feeds V GEMM)
    k_mma2<<<dim3(128, 4), 256, SMEM_BYTES>>>(pCS, pYf, pU, 512, 16384, 2048,
                                              2048, 16384, 16384, nullptr, nullptr, 1);
    k_fixup<<<4, 128>>>();
    // V = WINV @ U  (2048 x 16384 x 512) — V aliases Yf
    k_mma2<<<dim3(128, 16), 256, SMEM_BYTES>>>(pWINV, pU, pYf, 2048, 16384, 512,
                                               512, 16384, 16384, nullptr, nullptr, 0);
    // combine: V -> Z3, Z2 (rounded)
    k_combine<<<dim3(4, 1024), 128>>>(pYf);

    // outputs
    k_mma2<<<dim3(4, 256), 256, SMEM_BYTES>>>(pXr, pA1, out,        MTOT, 512, 512,
                                              512, 512, 1536, pu1, pw1, 0);
    k_mma2<<<dim3(4, 256), 256, SMEM_BYTES>>>(pZ2, pA2, out + 512,  MTOT, 512, 512,
                                              512, 512, 1536, pu2, pw2, 0);
    k_mma2<<<dim3(4, 256), 256, SMEM_BYTES>>>(pZ3, pA3, out + 1024, MTOT, 512, 512,
                                              512, 512, 1536, pu3, pw3, 0);
    (void)in_sizes; (void)n_in; (void)out_size;
}

// round 9
// speedup vs baseline: 4.2196x; 1.4833x over previous
#include <cuda_runtime.h>
#include <cuda_fp16.h>
#include <math.h>
#include <stdint.h>

#define MTOT 32768
#define LDIM 512

// ---------------- scratch (device globals; allocation-free) ----------------
__device__ __align__(128) float  g_TW[MTOT * 32 * 2];
__device__ __align__(128) __half g_CS[512 * 2048];
__device__ __align__(128) __half g_WINV[2048 * 512];   // cos/sin, NO 2/M scale
__device__ __align__(128) float  g_DL[512 * 512];
__device__ __align__(128) float  g_Q[512 * 512];
__device__ __align__(128) __half g_A1[512 * 512];
__device__ __align__(128) __half g_A2[512 * 512];
__device__ __align__(128) __half g_A3[512 * 512];
__device__ __align__(128) float  g_u1[MTOT];
__device__ __align__(128) float  g_u2[MTOT];
__device__ __align__(128) float  g_u3[MTOT];
__device__ __align__(128) float  g_w1[512];
__device__ __align__(128) float  g_w2[512];
__device__ __align__(128) float  g_w3[512];
__device__ __align__(128) __half g_Yfh[2048 * 16384];  // fold output
__device__ __align__(128) float  g_V[2048 * 16384];    // V (fp32)
__device__ __align__(128) __half g_U[512 * 16384];     // U (fp16)
__device__ __align__(128) __half g_Z2[MTOT * 512];
__device__ __align__(128) __half g_Z3[MTOT * 512];
__device__ __align__(128) __half g_Xr[MTOT * 512];

__device__ __forceinline__ uint32_t f2tf(float x) {
    uint32_t r;
    asm("cvt.rna.tf32.f32 %0, %1;" : "=r"(r) : "f"(x));
    return r;
}

__device__ __forceinline__ uint32_t smem_u32(const void* p) {
    uint32_t a;
    asm("{ .reg .u64 t; cvta.to.shared.u64 t, %1; cvt.u32.u64 %0, t; }" : "=r"(a) : "l"(p));
    return a;
}
__device__ __forceinline__ void cp16s(uint32_t saddr, const void* g) {
    asm volatile("cp.async.cg.shared.global [%0], [%1], 16;" :: "r"(saddr), "l"(g));
}
#define LDSM4(r0, r1, r2, r3, a)                                                   \
    asm volatile("ldmatrix.sync.aligned.m8n8.x4.shared.b16 {%0,%1,%2,%3}, [%4];"   \
                 : "=r"(r0), "=r"(r1), "=r"(r2), "=r"(r3) : "r"(a))
#define LDSM4T(r0, r1, r2, r3, a)                                                  \
    asm volatile("ldmatrix.sync.aligned.m8n8.x4.trans.shared.b16 {%0,%1,%2,%3}, [%4];" \
                 : "=r"(r0), "=r"(r1), "=r"(r2), "=r"(r3) : "r"(a))
#define HMMA(c, a, b)                                                              \
    asm volatile("mma.sync.aligned.m16n8k16.row.col.f32.f16.f16.f32 "              \
                 "{%0,%1,%2,%3}, {%4,%5,%6,%7}, {%8,%9}, {%0,%1,%2,%3};"           \
                 : "+f"((c)[0]), "+f"((c)[1]), "+f"((c)[2]), "+f"((c)[3])          \
                 : "r"((a)[0]), "r"((a)[1]), "r"((a)[2]), "r"((a)[3]),             \
                   "r"((b)[0]), "r"((b)[1]))

// ---------------- table builders ----------------
__global__ void k_build_tw() {
    int id = blockIdx.x * 256 + threadIdx.x;
    if (id >= MTOT * 32) return;
    int n = id >> 5, t = id & 31;
    int mm = ((2 * n + 1) * t) & 131071;
    float sn, cs;
    sincospif((float)mm * (1.0f / 65536.0f), &sn, &cs);
    g_TW[2 * id + 0] = cs;
    g_TW[2 * id + 1] = sn;
}

__global__ void k_build_cs() {
    int id = blockIdx.x * 256 + threadIdx.x;
    if (id >= 512 * 1024) return;
    int j = id >> 10, p = id & 1023;
    int mm = (j * (2 * p + 1)) & 2047;
    float sn, cs;
    sincospif((float)mm * (1.0f / 1024.0f), &sn, &cs);
    g_CS[j * 2048 + p] = __float2half(cs);
    g_CS[j * 2048 + 1024 + p] = __float2half(-sn);
    g_WINV[p * 512 + j] = __float2half(cs);
    g_WINV[(1024 + p) * 512 + j] = __float2half(sn);
}

__global__ void k_build_dl() {
    int id = blockIdx.x * 256 + threadIdx.x;
    if (id >= 512 * 512) return;
    int k = id >> 9, n = id & 511;
    int mm = (k * (2 * n + 1)) & 2047;
    float cs = cospif((float)mm * (1.0f / 1024.0f));
    float ck = (k == 0) ? 0.04419417382415922f : 0.0625f;
    g_DL[id] = ck * cs;
}

struct C2d { double x, y; };
__device__ __forceinline__ C2d cdiv(C2d a, C2d b) {
    double d = b.x * b.x + b.y * b.y;
    C2d r; r.x = (a.x * b.x + a.y * b.y) / d; r.y = (a.y * b.x - a.x * b.y) / d; return r;
}
__device__ __forceinline__ C2d cmul(C2d a, C2d b) {
    C2d r; r.x = a.x * b.x - a.y * b.y; r.y = a.x * b.y + a.y * b.x; return r;
}
__global__ void k_build_u() {
    int n = blockIdx.x * 256 + threadIdx.x;
    if (n >= MTOT) return;
    long on = 2L * n + 1;
    double s1, c1, s64, c64, s32, c32, s16, c16;
    sincospi((double)on / 65536.0, &s1, &c1);
    sincospi((double)(on & 2047) / 1024.0, &s64, &c64);
    sincospi((double)(on & 4095) / 2048.0, &s32, &c32);
    sincospi((double)(on & 8191) / 4096.0, &s16, &c16);
    C2d numer; numer.x = 1.0; numer.y = (n & 1) ? 1.0 : -1.0;
    C2d d1;  d1.x  = 1.0 - c1;  d1.y  = -s1;
    C2d d64; d64.x = 1.0 - c64; d64.y = -s64;
    C2d n32; n32.x = 1.0 - c32; n32.y = -s32;
    C2d n16; n16.x = 1.0 - c16; n16.y = -s16;
    double F1 = cdiv(numer, d1).x;
    C2d g = cdiv(numer, d64);
    double F2 = cmul(g, cdiv(n32, d1)).x;
    double F3 = cmul(g, cdiv(n16, d1)).x;
    const double C2M = 0.0078125;
    const double C1M = 0.005524271728019903;
    g_u1[n] = (float)(C2M * (F1 - 1.0) + C1M);
    g_u2[n] = (float)(C2M * (F2 - 1.0) + C1M);
    g_u3[n] = (float)(C2M * (F3 - 1.0) + C1M);
}

__global__ void k_build_w(int Kb, const float* __restrict__ b, float* __restrict__ w) {
    int c = blockIdx.x * 128 + threadIdx.x;
    if (c >= 512) return;
    float s = 0.f;
    for (int k = 0; k < Kb; k++) s += g_DL[k * 512 + c] * b[k];
    w[c] = s;
}

// ---------------- fold: X -> Yfh (fp16) + Xr (fp16) ----------------
__global__ void __launch_bounds__(128) k_fold(const float* __restrict__ X) {
    const int p = blockIdx.y;
    const int l = blockIdx.x * 128 + threadIdx.x;
    __shared__ float tw[32][64];
    for (int i = threadIdx.x; i < 2048; i += 128) {
        int q = i >> 6;
        tw[q][i & 63] = g_TW[(((long)(q << 10) + p)) * 64 + (i & 63)];
    }
    __syncthreads();
    float c[32], s[32];
#pragma unroll
    for (int t = 0; t < 32; t++) { c[t] = 0.f; s[t] = 0.f; }
    for (int q = 0; q < 32; q++) {
        int n = (q << 10) + p;
        float x = X[(long)n * 512 + l];
        g_Xr[(long)n * 512 + l] = __float2half(x);
#pragma unroll
        for (int t = 0; t < 32; t++) {
            c[t] += tw[q][2 * t] * x;
            s[t] += tw[q][2 * t + 1] * x;
        }
    }
#pragma unroll
    for (int t = 0; t < 32; t++) {
        g_Yfh[(long)p * 16384 + t * 512 + l] = __float2half(c[t]);
        g_Yfh[(long)(1024 + p) * 16384 + t * 512 + l] = __float2half(s[t]);
    }
}

// halve k=0 entries: U row j=0, first 512 cols (t=0)
__global__ void k_fixup() {
    int l = blockIdx.x * 128 + threadIdx.x;
    if (l < 512) g_U[l] = __float2half(__half2float(g_U[l]) * 0.5f);
}

// ---------------- combine: V -> Z3 (t<16), Z2 (t<32); applies 2/M ----------------
__global__ void __launch_bounds__(128) k_combine(const float* __restrict__ V) {
    const int p = blockIdx.y;
    const int l = blockIdx.x * 128 + threadIdx.x;
    __shared__ float tw[32][64];
    for (int i = threadIdx.x; i < 2048; i += 128) {
        int q = i >> 6;
        tw[q][i & 63] = g_TW[(((long)(q << 10) + p)) * 64 + (i & 63)];
    }
    __syncthreads();
    float vc[32], vs[32];
#pragma unroll
    for (int t = 0; t < 32; t++) {
        vc[t] = V[(long)p * 16384 + t * 512 + l];
        vs[t] = V[(long)(1024 + p) * 16384 + t * 512 + l];
    }
    const float SC = 2.0f / 32768.0f;
    for (int q = 0; q < 32; q++) {
        float acc = 0.f;
#pragma unroll
        for (int t = 0; t < 16; t++) acc += tw[q][2 * t] * vc[t] - tw[q][2 * t + 1] * vs[t];
        int n = (q << 10) + p;
        g_Z3[(long)n * 512 + l] = __float2half(acc * SC);
#pragma unroll
        for (int t = 16; t < 32; t++) acc += tw[q][2 * t] * vc[t] - tw[q][2 * t + 1] * vs[t];
        g_Z2[(long)n * 512 + l] = __float2half(acc * SC);
    }
}

// ---------------- small tf32 mma.sync GEMM (builder matrices) ----------------
__global__ void __launch_bounds__(256) k_mma(
    const float* __restrict__ A, const float* __restrict__ B, void* __restrict__ Cv,
    int M, int N, int K, int lda, int ldb, int ldc, int transA, int halfOut) {
    __shared__ uint32_t As[16][132];
    __shared__ uint32_t Bs[16][132];
    const int tid = threadIdx.x;
    const int wid = tid >> 5, lane = tid & 31;
    const int wm = wid & 1, wn = wid >> 1;
    const int g = lane >> 2, t4 = lane & 3;
    const int m0 = blockIdx.y * 128, n0 = blockIdx.x * 128;
    float acc[4][4][4];
#pragma unroll
    for (int i = 0; i < 4; i++)
#pragma unroll
        for (int j = 0; j < 4; j++)
#pragma unroll
            for (int r = 0; r < 4; r++) acc[i][j][r] = 0.f;
    const int bk = tid >> 4, bn = (tid & 15) * 8;
    const int ar = tid >> 1, ak = (tid & 1) * 8;
    for (int k0 = 0; k0 < K; k0 += 16) {
        const float* Ap;
        if (transA) Ap = A + (long)(k0 + bk) * lda + m0 + bn;
        else        Ap = A + (long)(m0 + ar) * lda + k0 + ak;
        float4 pa0 = *(const float4*)(Ap);
        float4 pa1 = *(const float4*)(Ap + 4);
        const float* Bp = B + (long)(k0 + bk) * ldb + n0 + bn;
        float4 pb0 = *(const float4*)(Bp);
        float4 pb1 = *(const float4*)(Bp + 4);
        if (transA) {
            uint4 v0, v1;
            v0.x = f2tf(pa0.x); v0.y = f2tf(pa0.y); v0.z = f2tf(pa0.z); v0.w = f2tf(pa0.w);
            v1.x = f2tf(pa1.x); v1.y = f2tf(pa1.y); v1.z = f2tf(pa1.z); v1.w = f2tf(pa1.w);
            *(uint4*)&As[bk][bn] = v0;
            *(uint4*)&As[bk][bn + 4] = v1;
        } else {
            As[ak + 0][ar] = f2tf(pa0.x);
            As[ak + 1][ar] = f2tf(pa0.y);
            As[ak + 2][ar] = f2tf(pa0.z);
            As[ak + 3][ar] = f2tf(pa0.w);
            As[ak + 4][ar] = f2tf(pa1.x);
            As[ak + 5][ar] = f2tf(pa1.y);
            As[ak + 6][ar] = f2tf(pa1.z);
            As[ak + 7][ar] = f2tf(pa1.w);
        }
        {
            uint4 v0, v1;
            v0.x = f2tf(pb0.x); v0.y = f2tf(pb0.y); v0.z = f2tf(pb0.z); v0.w = f2tf(pb0.w);
            v1.x = f2tf(pb1.x); v1.y = f2tf(pb1.y); v1.z = f2tf(pb1.z); v1.w = f2tf(pb1.w);
            *(uint4*)&Bs[bk][bn] = v0;
            *(uint4*)&Bs[bk][bn + 4] = v1;
        }
        __syncthreads();
#pragma unroll
        for (int ks = 0; ks < 2; ks++) {
            const int kb = ks * 8;
            uint32_t a[4][4], b[4][2];
#pragma unroll
            for (int mi = 0; mi < 4; mi++) {
                int row = wm * 64 + mi * 16 + g;
                a[mi][0] = As[kb + t4][row];
                a[mi][1] = As[kb + t4][row + 8];
                a[mi][2] = As[kb + t4 + 4][row];
                a[mi][3] = As[kb + t4 + 4][row + 8];
            }
#pragma unroll
            for (int nj = 0; nj < 4; nj++) {
                int col = wn * 32 + nj * 8 + g;
                b[nj][0] = Bs[kb + t4][col];
                b[nj][1] = Bs[kb + t4 + 4][col];
            }
#pragma unroll
            for (int mi = 0; mi < 4; mi++)
#pragma unroll
                for (int nj = 0; nj < 4; nj++) {
                    asm("mma.sync.aligned.m16n8k8.row.col.f32.tf32.tf32.f32 "
                        "{%0,%1,%2,%3}, {%4,%5,%6,%7}, {%8,%9}, {%0,%1,%2,%3};"
                        : "+f"(acc[mi][nj][0]), "+f"(acc[mi][nj][1]),
                          "+f"(acc[mi][nj][2]), "+f"(acc[mi][nj][3])
                        : "r"(a[mi][0]), "r"(a[mi][1]), "r"(a[mi][2]), "r"(a[mi][3]),
                          "r"(b[nj][0]), "r"(b[nj][1]));
                }
        }
        __syncthreads();
    }
#pragma unroll
    for (int mi = 0; mi < 4; mi++) {
        int r = wm * 64 + mi * 16 + g;
#pragma unroll
        for (int nj = 0; nj < 4; nj++) {
            int c = wn * 32 + nj * 8 + t4 * 2;
            if (halfOut) {
                __half* Ch = (__half*)Cv;
                __half2 h0, h1;
                h0.x = __float2half(acc[mi][nj][0]); h0.y = __float2half(acc[mi][nj][1]);
                h1.x = __float2half(acc[mi][nj][2]); h1.y = __float2half(acc[mi][nj][3]);
                *(__half2*)(Ch + (long)(m0 + r) * ldc + n0 + c) = h0;
                *(__half2*)(Ch + (long)(m0 + r + 8) * ldc + n0 + c) = h1;
            } else {
                float* C = (float*)Cv;
                float2 v0, v1;
                v0.x = acc[mi][nj][0]; v0.y = acc[mi][nj][1];
                v1.x = acc[mi][nj][2]; v1.y = acc[mi][nj][3];
                *(float2*)(C + (long)(m0 + r) * ldc + n0 + c) = v0;
                *(float2*)(C + (long)(m0 + r + 8) * ldc + n0 + c) = v1;
            }
        }
    }
}

// ---------------- pipelined fp16 GEMM (LDSM + HMMA) ----------------
// C[M,N] = A[M,K]*B[K,N] (+ u w^T). BM=BN=128, BK=32 halves, 4-stage cp.async.
#define SA_STRIDE 40     // halves per A row (80B, conflict-free ldsm)
#define SB_STRIDE 136    // halves per B row (272B)
#define SA_BYTES (128 * SA_STRIDE * 2)   // 10240
#define SB_BYTES (32 * SB_STRIDE * 2)    // 8704
#define H_STAGE (SA_BYTES + SB_BYTES)    // 18944
#define H_NSTG 4
#define H_SMEM (H_NSTG * H_STAGE)        // 75776

__global__ void __launch_bounds__(256, 2) k_hgemm(
    const __half* __restrict__ A, const __half* __restrict__ B, void* __restrict__ Cv,
    int M, int N, int K, int lda, int ldb, int ldc,
    const float* __restrict__ u, const float* __restrict__ w, int halfOut) {
    extern __shared__ __align__(16) char hs[];
    const uint32_t base = smem_u32(hs);
    const int tid = threadIdx.x;
    const int wid = tid >> 5, lane = tid & 31;
    const int wm = wid & 1, wn = wid >> 1;
    const int g = lane >> 2, t4 = lane & 3;
    const int m0 = blockIdx.y * 128, n0 = blockIdx.x * 128;
    const int KT = K >> 5;

    const int arow = tid >> 2, acol = (tid & 3) * 8;   // A: 2 chunks (rows +0,+64)
    const int brow = tid >> 4, bcol = (tid & 15) * 8;  // B: 2 chunks (k +0,+16)

    float acc[4][4][4];
#pragma unroll
    for (int i = 0; i < 4; i++)
#pragma unroll
        for (int j = 0; j < 4; j++)
#pragma unroll
            for (int r = 0; r < 4; r++) acc[i][j][r] = 0.f;

#define H_ISSUE(st, kt) do {                                                       \
        uint32_t _a = base + (st) * H_STAGE;                                       \
        uint32_t _b = _a + SA_BYTES;                                               \
        long _k = (long)(kt) << 5;                                                 \
        cp16s(_a + (arow * SA_STRIDE + acol) * 2,                                  \
              A + (long)(m0 + arow) * lda + _k + acol);                            \
        cp16s(_a + ((arow + 64) * SA_STRIDE + acol) * 2,                           \
              A + (long)(m0 + arow + 64) * lda + _k + acol);                       \
        cp16s(_b + (brow * SB_STRIDE + bcol) * 2,                                  \
              B + (_k + brow) * ldb + n0 + bcol);                                  \
        cp16s(_b + ((brow + 16) * SB_STRIDE + bcol) * 2,                           \
              B + (_k + brow + 16) * ldb + n0 + bcol);                             \
        asm volatile("cp.async.commit_group;");                                    \
    } while (0)

#pragma unroll
    for (int s = 0; s < H_NSTG - 1; s++)
        if (s < KT) H_ISSUE(s, s);

    for (int kt = 0; kt < KT; kt++) {
        asm volatile("cp.async.wait_group %0;" :: "n"(H_NSTG - 2));
        __syncthreads();
        int nt = kt + H_NSTG - 1;
        if (nt < KT) H_ISSUE(nt & (H_NSTG - 1), nt);
        const uint32_t sa = base + (kt & (H_NSTG - 1)) * H_STAGE;
        const uint32_t sb = sa + SA_BYTES;
#pragma unroll
        for (int ks = 0; ks < 2; ks++) {
            uint32_t a[4][4], b[4][2];
#pragma unroll
            for (int mi = 0; mi < 4; mi++) {
                uint32_t ad = sa + (((wm * 64 + mi * 16 + (lane & 15)) * SA_STRIDE)
                                    + ks * 16 + (lane >> 4) * 8) * 2;
                LDSM4(a[mi][0], a[mi][1], a[mi][2], a[mi][3], ad);
            }
#pragma unroll
            for (int njp = 0; njp < 2; njp++) {
                uint32_t bd = sb + (((ks * 16 + (lane & 15)) * SB_STRIDE)
                                    + wn * 32 + njp * 16 + (lane >> 4) * 8) * 2;
                uint32_t r0, r1, r2, r3;
                LDSM4T(r0, r1, r2, r3, bd);
                b[2 * njp][0] = r0; b[2 * njp][1] = r1;
                b[2 * njp + 1][0] = r2; b[2 * njp + 1][1] = r3;
            }
#pragma unroll
            for (int mi = 0; mi < 4; mi++)
#pragma unroll
                for (int nj = 0; nj < 4; nj++)
                    HMMA(acc[mi][nj], a[mi], b[nj]);
        }
        __syncthreads();
    }

    const bool r1 = (u != nullptr);
#pragma unroll
    for (int mi = 0; mi < 4; mi++) {
        int r = wm * 64 + mi * 16 + g;
        float u0 = 0.f, u1 = 0.f;
        if (r1) { u0 = u[m0 + r]; u1 = u[m0 + r + 8]; }
#pragma unroll
        for (int nj = 0; nj < 4; nj++) {
            int c = wn * 32 + nj * 8 + t4 * 2;
            float w0 = 0.f, w1 = 0.f;
            if (r1) { w0 = w[n0 + c]; w1 = w[n0 + c + 1]; }
            float v00 = acc[mi][nj][0] + u0 * w0;
            float v01 = acc[mi][nj][1] + u0 * w1;
            float v10 = acc[mi][nj][2] + u1 * w0;
            float v11 = acc[mi][nj][3] + u1 * w1;
            if (halfOut) {
                __half* Ch = (__half*)Cv;
                __half2 h0, h1;
                h0.x = __float2half(v00); h0.y = __float2half(v01);
                h1.x = __float2half(v10); h1.y = __float2half(v11);
                *(__half2*)(Ch + (long)(m0 + r) * ldc + n0 + c) = h0;
                *(__half2*)(Ch + (long)(m0 + r + 8) * ldc + n0 + c) = h1;
            } else {
                float* C = (float*)Cv;
                float2 f0, f1;
                f0.x = v00; f0.y = v01;
                f1.x = v10; f1.y = v11;
                *(float2*)(C + (long)(m0 + r) * ldc + n0 + c) = f0;
                *(float2*)(C + (long)(m0 + r + 8) * ldc + n0 + c) = f1;
            }
        }
    }
}

// ---------------- launch ----------------
extern "C" void kernel_launch(void* const* d_in, const int* in_sizes, int n_in,
                              void* d_out, int out_size) {
    const float* X  = (const float*)d_in[0];
    const float* W1 = (const float*)d_in[1];
    const float* b1 = (const float*)d_in[2];
    const float* W2 = (const float*)d_in[3];
    const float* b2 = (const float*)d_in[4];
    const float* W3 = (const float*)d_in[5];
    const float* b3 = (const float*)d_in[6];
    float* out = (float*)d_out;

    __half *pCS, *pWINV, *pA1, *pA2, *pA3, *pYfh, *pU, *pZ2, *pZ3, *pXr;
    float *pDL, *pQ, *pu1, *pu2, *pu3, *pw1, *pw2, *pw3, *pV;
    cudaGetSymbolAddress((void**)&pCS, g_CS);
    cudaGetSymbolAddress((void**)&pWINV, g_WINV);
    cudaGetSymbolAddress((void**)&pDL, g_DL);
    cudaGetSymbolAddress((void**)&pQ, g_Q);
    cudaGetSymbolAddress((void**)&pA1, g_A1);
    cudaGetSymbolAddress((void**)&pA2, g_A2);
    cudaGetSymbolAddress((void**)&pA3, g_A3);
    cudaGetSymbolAddress((void**)&pu1, g_u1);
    cudaGetSymbolAddress((void**)&pu2, g_u2);
    cudaGetSymbolAddress((void**)&pu3, g_u3);
    cudaGetSymbolAddress((void**)&pw1, g_w1);
    cudaGetSymbolAddress((void**)&pw2, g_w2);
    cudaGetSymbolAddress((void**)&pw3, g_w3);
    cudaGetSymbolAddress((void**)&pYfh, g_Yfh);
    cudaGetSymbolAddress((void**)&pV, g_V);
    cudaGetSymbolAddress((void**)&pU, g_U);
    cudaGetSymbolAddress((void**)&pZ2, g_Z2);
    cudaGetSymbolAddress((void**)&pZ3, g_Z3);
    cudaGetSymbolAddress((void**)&pXr, g_Xr);

    cudaFuncSetAttribute(k_hgemm, cudaFuncAttributeMaxDynamicSharedMemorySize, H_SMEM);

    // launches 1-5 (so #6 = U GEMM gets profiled by ncu -s 5 -c 1)
    k_build_tw<<<(MTOT * 32) / 256, 256>>>();
    k_build_cs<<<(512 * 1024) / 256, 256>>>();
    k_build_dl<<<(512 * 512) / 256, 256>>>();
    k_build_u<<<MTOT / 256, 256>>>();
    k_fold<<<dim3(4, 1024), 128>>>(X);

    // #6: U = CS[512x2048] @ Yfh[2048x16384]  -> half
    k_hgemm<<<dim3(128, 4), 256, H_SMEM>>>(pCS, pYfh, pU, 512, 16384, 2048,
                                           2048, 16384, 16384, nullptr, nullptr, 1);
    k_fixup<<<4, 128>>>();
    k_build_w<<<4, 128>>>(512, b1, pw1);
    k_build_w<<<4, 128>>>(256, b2, pw2);
    k_build_w<<<4, 128>>>(128, b3, pw3);

    // builders (tf32): Q = Wk @ DL[0:Kk]; Ak = Q^T @ DL  (half out)
    k_mma<<<dim3(4, 4), 256>>>(W1, pDL, pQ, 512, 512, 512, 512, 512, 512, 0, 0);
    k_mma<<<dim3(4, 4), 256>>>(pQ, pDL, pA1, 512, 512, 512, 512, 512, 512, 1, 1);
    k_mma<<<dim3(4, 2), 256>>>(W2, pDL, pQ, 256, 512, 256, 256, 512, 512, 0, 0);
    k_mma<<<dim3(4, 4), 256>>>(pQ, pDL, pA2, 512, 512, 256, 512, 512, 512, 1, 1);
    k_mma<<<dim3(4, 1), 256>>>(W3, pDL, pQ, 128, 512, 128, 128, 512, 512, 0, 0);
    k_mma<<<dim3(4, 4), 256>>>(pQ, pDL, pA3, 512, 512, 128, 512, 512, 512, 1, 1);

    // V = WINV[2048x512] @ U[512x16384] -> fp32
    k_hgemm<<<dim3(128, 16), 256, H_SMEM>>>(pWINV, pU, pV, 2048, 16384, 512,
                                            512, 16384, 16384, nullptr, nullptr, 0);
    k_combine<<<dim3(4, 1024), 128>>>(pV);

    // outputs
    k_hgemm<<<dim3(4, 256), 256, H_SMEM>>>(pXr, pA1, out,        MTOT, 512, 512,
                                           512, 512, 1536, pu1, pw1, 0);
    k_hgemm<<<dim3(4, 256), 256, H_SMEM>>>(pZ2, pA2, out + 512,  MTOT, 512, 512,
                                           512, 512, 1536, pu2, pw2, 0);
    k_hgemm<<<dim3(4, 256), 256, H_SMEM>>>(pZ3, pA3, out + 1024, MTOT, 512, 512,
                                           512, 512, 1536, pu3, pw3, 0);
    (void)in_sizes; (void)n_in; (void)out_size;
}